// round 2
// baseline (speedup 1.0000x reference)
#include <cuda_runtime.h>

#define B_    16
#define CL_   512
#define N_    3136
#define NV_   (N_ / 4)        // 784 float4 per row
#define TILES 25              // ceil(3136 / 128)
#define TPB_R 128             // reduce block size

// Scratch (__device__ globals — allocation-free rule)
__device__ float d_g[B_ * N_];          // g[b,n]
__device__ float d_part[B_ * TILES];    // per-tile partial sums of t

// Pass 1: t[b,n] = sum_c x[b,c,n]*theta_w[c]; g[b,n] = sum_c x[b,c,n]*g_w[c]
// Store g; block-reduce t into d_part[b][tile] (no atomics, deterministic).
__global__ __launch_bounds__(TPB_R) void reduce_kernel(
    const float* __restrict__ x,
    const float* __restrict__ theta_w,
    const float* __restrict__ g_w)
{
    __shared__ float s_tw[CL_];
    __shared__ float s_gw[CL_];
    __shared__ float s_warp[TPB_R / 32];

    const int b    = blockIdx.y;
    const int tile = blockIdx.x;
    const int n    = tile * TPB_R + threadIdx.x;

    for (int c = threadIdx.x; c < CL_; c += TPB_R) {
        s_tw[c] = theta_w[c];
        s_gw[c] = g_w[c];
    }
    __syncthreads();

    float t = 0.0f, g = 0.0f;
    if (n < N_) {
        const float* xp = x + (size_t)b * CL_ * N_ + n;
        #pragma unroll 8
        for (int c = 0; c < CL_; c++) {
            float v = __ldg(&xp[(size_t)c * N_]);
            t = fmaf(v, s_tw[c], t);
            g = fmaf(v, s_gw[c], g);
        }
        d_g[b * N_ + n] = g;
    }

    // warp-shuffle reduce t, then across the 4 warps via smem
    #pragma unroll
    for (int off = 16; off > 0; off >>= 1)
        t += __shfl_down_sync(0xFFFFFFFFu, t, off);
    if ((threadIdx.x & 31) == 0) s_warp[threadIdx.x >> 5] = t;
    __syncthreads();
    if (threadIdx.x == 0) {
        float s = 0.0f;
        #pragma unroll
        for (int w = 0; w < TPB_R / 32; w++) s += s_warp[w];
        d_part[b * TILES + tile] = s;
    }
}

// Pass 2: out[b,c,n] = x + g[b,n] * (tsum[b]/N) * h_w[c] + h_b[c]
// Traverse in REVERSE so first reads hit the L2-resident tail of x from pass 1.
__global__ __launch_bounds__(256) void out_kernel(
    const float* __restrict__ x,
    const float* __restrict__ h_w,
    const float* __restrict__ h_b,
    float* __restrict__ out)
{
    const int total = B_ * CL_ * NV_;                      // 6,422,528 vec4
    const int v = total - 1 - (blockIdx.x * blockDim.x + threadIdx.x);

    const int n4  = v % NV_;
    const int row = v / NV_;          // row = b*CL + c (constant b per block: 256 | 401408)
    const int c   = row % CL_;
    const int b   = row / CL_;

    // block leader sums the 25 partials for this block's (single) b
    __shared__ float s_mt;
    if (threadIdx.x == 0) {
        float s = 0.0f;
        #pragma unroll
        for (int i = 0; i < TILES; i++) s += d_part[b * TILES + i];
        s_mt = s * (1.0f / (float)N_);
    }
    __syncthreads();
    const float mt = s_mt;

    const float hwc = h_w[c] * mt;
    const float hbc = h_b[c];

    const float4 g4 = *reinterpret_cast<const float4*>(&d_g[b * N_ + n4 * 4]);
    const float4 x4 = __ldcs(reinterpret_cast<const float4*>(x) + v);   // last use of x

    float4 o;
    o.x = fmaf(g4.x, hwc, x4.x) + hbc;
    o.y = fmaf(g4.y, hwc, x4.y) + hbc;
    o.z = fmaf(g4.z, hwc, x4.z) + hbc;
    o.w = fmaf(g4.w, hwc, x4.w) + hbc;

    __stcs(reinterpret_cast<float4*>(out) + v, o);          // streaming store
}

extern "C" void kernel_launch(void* const* d_in, const int* in_sizes, int n_in,
                              void* d_out, int out_size)
{
    const float* x       = (const float*)d_in[0];
    const float* theta_w = (const float*)d_in[1];
    const float* g_w     = (const float*)d_in[2];
    const float* h_w     = (const float*)d_in[3];
    const float* h_b     = (const float*)d_in[4];
    float*       out     = (float*)d_out;

    dim3 grid1(TILES, B_);                 // 25 x 16 = 400 blocks
    reduce_kernel<<<grid1, TPB_R>>>(x, theta_w, g_w);

    const int total_vec4 = B_ * CL_ * NV_; // 6,422,528
    out_kernel<<<total_vec4 / 256, 256>>>(x, h_w, h_b, out);
}

// round 3
// speedup vs baseline: 1.6476x; 1.6476x over previous
#include <cuda_runtime.h>

#define B_      16
#define CL_     512
#define N_      3136
#define NV_     (N_ / 4)       // 784 float4 per row
#define V4T     64             // float4 per tile (per block) in pass 1
#define TILES_R 13             // ceil(784 / 64)
#define NGRP    4              // c-groups per block (each handles CL_/NGRP = 128 c)
#define CGRP    (CL_ / NGRP)   // 128

// Scratch (__device__ globals — allocation-free rule)
__device__ float4 d_g4[B_ * NV_];          // g[b, n] as float4
__device__ float  d_part[B_ * TILES_R];    // per-tile partial sums of t

// Pass 1 (vectorized): each block = (b, tile of 64 float4 n's) x full c.
// 256 threads = 4 groups x 64; group gr handles c in [gr*128, gr*128+128).
// float4 loads -> 4x memory-level parallelism vs scalar version.
__global__ __launch_bounds__(256) void reduce_kernel(
    const float* __restrict__ x,
    const float* __restrict__ theta_w,
    const float* __restrict__ g_w)
{
    __shared__ float  s_tw[CL_];
    __shared__ float  s_gw[CL_];
    __shared__ float4 s_g[256];
    __shared__ float  s_warp[8];

    const int b    = blockIdx.y;
    const int tile = blockIdx.x;
    const int gr   = threadIdx.x >> 6;          // 0..3
    const int ln   = threadIdx.x & 63;          // 0..63
    const int n4   = tile * V4T + ln;
    const bool valid = (n4 < NV_);

    for (int c = threadIdx.x; c < CL_; c += 256) {
        s_tw[c] = theta_w[c];
        s_gw[c] = g_w[c];
    }
    __syncthreads();

    const float4* x4 = reinterpret_cast<const float4*>(x) + (size_t)b * CL_ * NV_;

    float  t  = 0.0f;
    float4 g4 = make_float4(0.f, 0.f, 0.f, 0.f);

    if (valid) {
        const int c0 = gr * CGRP;
        const float4* xp = x4 + (size_t)c0 * NV_ + n4;
        #pragma unroll 8
        for (int c = 0; c < CGRP; c++) {
            float4 v  = __ldg(xp + (size_t)c * NV_);
            float  tw = s_tw[c0 + c];
            float  gw = s_gw[c0 + c];
            t = fmaf(v.x + v.y + v.z + v.w, tw, t);
            g4.x = fmaf(v.x, gw, g4.x);
            g4.y = fmaf(v.y, gw, g4.y);
            g4.z = fmaf(v.z, gw, g4.z);
            g4.w = fmaf(v.w, gw, g4.w);
        }
    }

    // ---- combine g across the 4 c-groups (smem) ----
    s_g[threadIdx.x] = g4;
    __syncthreads();
    if (threadIdx.x < V4T && valid) {
        float4 a = s_g[threadIdx.x];
        float4 bb = s_g[threadIdx.x + 64];
        float4 cc = s_g[threadIdx.x + 128];
        float4 dd = s_g[threadIdx.x + 192];
        float4 o;
        o.x = a.x + bb.x + cc.x + dd.x;
        o.y = a.y + bb.y + cc.y + dd.y;
        o.z = a.z + bb.z + cc.z + dd.z;
        o.w = a.w + bb.w + cc.w + dd.w;
        d_g4[b * NV_ + n4] = o;
    }

    // ---- reduce t across the whole block ----
    #pragma unroll
    for (int off = 16; off > 0; off >>= 1)
        t += __shfl_down_sync(0xFFFFFFFFu, t, off);
    if ((threadIdx.x & 31) == 0) s_warp[threadIdx.x >> 5] = t;
    __syncthreads();
    if (threadIdx.x == 0) {
        float s = 0.0f;
        #pragma unroll
        for (int w = 0; w < 8; w++) s += s_warp[w];
        d_part[b * TILES_R + tile] = s;
    }
}

// Pass 2 (unchanged from measured-36.6us version, TILES updated):
// out[b,c,n] = x + g[b,n] * (tsum[b]/N) * h_w[c] + h_b[c]
// Reverse traversal so first reads hit the L2-resident tail of x from pass 1.
__global__ __launch_bounds__(256) void out_kernel(
    const float* __restrict__ x,
    const float* __restrict__ h_w,
    const float* __restrict__ h_b,
    float* __restrict__ out)
{
    const int total = B_ * CL_ * NV_;                      // 6,422,528 vec4
    const int v = total - 1 - (blockIdx.x * blockDim.x + threadIdx.x);

    const int n4  = v % NV_;
    const int row = v / NV_;          // row = b*CL + c
    const int c   = row % CL_;
    const int b   = row / CL_;

    __shared__ float s_mt;
    if (threadIdx.x == 0) {
        float s = 0.0f;
        #pragma unroll
        for (int i = 0; i < TILES_R; i++) s += d_part[b * TILES_R + i];
        s_mt = s * (1.0f / (float)N_);
    }
    __syncthreads();
    const float mt = s_mt;

    const float hwc = h_w[c] * mt;
    const float hbc = h_b[c];

    const float4 g4 = d_g4[b * NV_ + n4];
    const float4 x4 = __ldcs(reinterpret_cast<const float4*>(x) + v);   // last use of x

    float4 o;
    o.x = fmaf(g4.x, hwc, x4.x) + hbc;
    o.y = fmaf(g4.y, hwc, x4.y) + hbc;
    o.z = fmaf(g4.z, hwc, x4.z) + hbc;
    o.w = fmaf(g4.w, hwc, x4.w) + hbc;

    __stcs(reinterpret_cast<float4*>(out) + v, o);          // streaming store
}

extern "C" void kernel_launch(void* const* d_in, const int* in_sizes, int n_in,
                              void* d_out, int out_size)
{
    const float* x       = (const float*)d_in[0];
    const float* theta_w = (const float*)d_in[1];
    const float* g_w     = (const float*)d_in[2];
    const float* h_w     = (const float*)d_in[3];
    const float* h_b     = (const float*)d_in[4];
    float*       out     = (float*)d_out;

    dim3 grid1(TILES_R, B_);               // 13 x 16 = 208 blocks, 256 threads
    reduce_kernel<<<grid1, 256>>>(x, theta_w, g_w);

    const int total_vec4 = B_ * CL_ * NV_; // 6,422,528
    out_kernel<<<total_vec4 / 256, 256>>>(x, h_w, h_b, out);
}

// round 4
// speedup vs baseline: 1.7219x; 1.0451x over previous
#include <cuda_runtime.h>

#define B_      16
#define CL_     512
#define N_      3136
#define NV_     (N_ / 4)        // 784 float4 per row
#define V4T     64              // float4 columns per tile (pass 1)
#define TILES_R 13              // ceil(784 / 64)
#define NCHUNK  4               // c-chunks across blocks
#define CCHUNK  (CL_ / NCHUNK)  // 128 c per chunk
#define CSUB    (CCHUNK / 4)    // 32 c per intra-block group
#define NPART   (NCHUNK * TILES_R)  // 52 t-partials per b

// Scratch (__device__ globals — allocation-free rule)
__device__ float4 d_g4p[NCHUNK * B_ * NV_];   // per-chunk partial g  (~800 KB)
__device__ float  d_part[B_ * NPART];         // per-(chunk,tile) partial sums of t

// Pass 1: grid (13, 16, 4) x 256 threads. Block = (n-tile of 64 float4, b, c-chunk).
// 256 threads = 4 groups x 64 lanes; group gr handles 32 c of this chunk.
__global__ __launch_bounds__(256) void reduce_kernel(
    const float* __restrict__ x,
    const float* __restrict__ theta_w,
    const float* __restrict__ g_w)
{
    __shared__ float  s_tw[CCHUNK];
    __shared__ float  s_gw[CCHUNK];
    __shared__ float4 s_g[256];
    __shared__ float  s_warp[8];

    const int tile  = blockIdx.x;
    const int b     = blockIdx.y;
    const int chunk = blockIdx.z;
    const int gr    = threadIdx.x >> 6;          // 0..3
    const int ln    = threadIdx.x & 63;          // 0..63
    const int n4    = tile * V4T + ln;
    const bool valid = (n4 < NV_);
    const int cbase = chunk * CCHUNK;

    if (threadIdx.x < CCHUNK) {
        s_tw[threadIdx.x] = theta_w[cbase + threadIdx.x];
        s_gw[threadIdx.x] = g_w[cbase + threadIdx.x];
    }
    __syncthreads();

    const float4* x4 = reinterpret_cast<const float4*>(x) + (size_t)b * CL_ * NV_;

    float  t  = 0.0f;
    float4 g4 = make_float4(0.f, 0.f, 0.f, 0.f);

    if (valid) {
        const int cl0 = gr * CSUB;               // local c offset within chunk
        const float4* xp = x4 + (size_t)(cbase + cl0) * NV_ + n4;
        #pragma unroll 8
        for (int c = 0; c < CSUB; c++) {
            float4 v  = __ldg(xp + (size_t)c * NV_);
            float  tw = s_tw[cl0 + c];
            float  gw = s_gw[cl0 + c];
            t = fmaf(v.x + v.y + v.z + v.w, tw, t);
            g4.x = fmaf(v.x, gw, g4.x);
            g4.y = fmaf(v.y, gw, g4.y);
            g4.z = fmaf(v.z, gw, g4.z);
            g4.w = fmaf(v.w, gw, g4.w);
        }
    }

    // combine g across the 4 intra-block c-groups
    s_g[threadIdx.x] = g4;
    __syncthreads();
    if (threadIdx.x < V4T && valid) {
        float4 a  = s_g[threadIdx.x];
        float4 bb = s_g[threadIdx.x + 64];
        float4 cc = s_g[threadIdx.x + 128];
        float4 dd = s_g[threadIdx.x + 192];
        float4 o;
        o.x = a.x + bb.x + cc.x + dd.x;
        o.y = a.y + bb.y + cc.y + dd.y;
        o.z = a.z + bb.z + cc.z + dd.z;
        o.w = a.w + bb.w + cc.w + dd.w;
        d_g4p[(chunk * B_ + b) * NV_ + n4] = o;
    }

    // reduce t across the block -> one partial
    #pragma unroll
    for (int off = 16; off > 0; off >>= 1)
        t += __shfl_down_sync(0xFFFFFFFFu, t, off);
    if ((threadIdx.x & 31) == 0) s_warp[threadIdx.x >> 5] = t;
    __syncthreads();
    if (threadIdx.x == 0) {
        float s = 0.0f;
        #pragma unroll
        for (int w = 0; w < 8; w++) s += s_warp[w];
        d_part[b * NPART + chunk * TILES_R + tile] = s;
    }
}

// Pass 2: out[b,c,n] = x + g[b,n] * (tsum[b]/N) * h_w[c] + h_b[c]
// Combines the 4 per-chunk g partials (L2-resident). Reverse traversal so first
// reads hit the L2-resident tail of x from pass 1.
__global__ __launch_bounds__(256) void out_kernel(
    const float* __restrict__ x,
    const float* __restrict__ h_w,
    const float* __restrict__ h_b,
    float* __restrict__ out)
{
    const int total = B_ * CL_ * NV_;                      // 6,422,528 vec4
    const int v = total - 1 - (blockIdx.x * blockDim.x + threadIdx.x);

    const int n4  = v % NV_;
    const int row = v / NV_;          // row = b*CL + c
    const int c   = row % CL_;
    const int b   = row / CL_;

    __shared__ float s_mt;
    if (threadIdx.x == 0) {
        float s = 0.0f;
        #pragma unroll
        for (int i = 0; i < NPART; i++) s += d_part[b * NPART + i];
        s_mt = s * (1.0f / (float)N_);
    }
    __syncthreads();
    const float mt = s_mt;

    const float hwc = h_w[c] * mt;
    const float hbc = h_b[c];

    const int gi = b * NV_ + n4;
    float4 p0 = d_g4p[0 * B_ * NV_ + gi];
    float4 p1 = d_g4p[1 * B_ * NV_ + gi];
    float4 p2 = d_g4p[2 * B_ * NV_ + gi];
    float4 p3 = d_g4p[3 * B_ * NV_ + gi];
    float4 g4;
    g4.x = (p0.x + p1.x) + (p2.x + p3.x);
    g4.y = (p0.y + p1.y) + (p2.y + p3.y);
    g4.z = (p0.z + p1.z) + (p2.z + p3.z);
    g4.w = (p0.w + p1.w) + (p2.w + p3.w);

    const float4 x4 = __ldcs(reinterpret_cast<const float4*>(x) + v);   // last use of x

    float4 o;
    o.x = fmaf(g4.x, hwc, x4.x) + hbc;
    o.y = fmaf(g4.y, hwc, x4.y) + hbc;
    o.z = fmaf(g4.z, hwc, x4.z) + hbc;
    o.w = fmaf(g4.w, hwc, x4.w) + hbc;

    __stcs(reinterpret_cast<float4*>(out) + v, o);          // streaming store
}

extern "C" void kernel_launch(void* const* d_in, const int* in_sizes, int n_in,
                              void* d_out, int out_size)
{
    const float* x       = (const float*)d_in[0];
    const float* theta_w = (const float*)d_in[1];
    const float* g_w     = (const float*)d_in[2];
    const float* h_w     = (const float*)d_in[3];
    const float* h_b     = (const float*)d_in[4];
    float*       out     = (float*)d_out;

    dim3 grid1(TILES_R, B_, NCHUNK);       // 13 x 16 x 4 = 832 blocks
    reduce_kernel<<<grid1, 256>>>(x, theta_w, g_w);

    const int total_vec4 = B_ * CL_ * NV_; // 6,422,528
    out_kernel<<<total_vec4 / 256, 256>>>(x, h_w, h_b, out);
}

// round 5
// speedup vs baseline: 2.1802x; 1.2662x over previous
#include <cuda_runtime.h>

#define B_      16
#define CL_     512
#define N_      3136
#define NV_     (N_ / 4)        // 784 float4 per row
#define V4T     64              // float4 columns per tile (pass 1)
#define TILES_R 13              // ceil(784 / 64)
#define NCHUNK  4               // c-chunks across blocks
#define CCHUNK  (CL_ / NCHUNK)  // 128 c per chunk
#define CSUB    (CCHUNK / 4)    // 32 c per intra-block group
#define NPART   (NCHUNK * TILES_R)  // 52 t-partials per b

// Scratch (__device__ globals — allocation-free rule)
__device__ float4 d_g4p[NCHUNK * B_ * NV_];   // per-chunk partial g (~800 KB)
__device__ float4 d_g4[B_ * NV_];             // folded g (~200 KB)
__device__ float  d_part[B_ * NPART];         // per-(chunk,tile) partial sums of t
__device__ float  d_mt[B_];                   // mean(t) per batch

// Pass 1: grid (13, 16, 4) x 256 threads. Block = (n-tile of 64 float4, b, c-chunk).
__global__ __launch_bounds__(256) void reduce_kernel(
    const float* __restrict__ x,
    const float* __restrict__ theta_w,
    const float* __restrict__ g_w)
{
    __shared__ float  s_tw[CCHUNK];
    __shared__ float  s_gw[CCHUNK];
    __shared__ float4 s_g[256];
    __shared__ float  s_warp[8];

    const int tile  = blockIdx.x;
    const int b     = blockIdx.y;
    const int chunk = blockIdx.z;
    const int gr    = threadIdx.x >> 6;          // 0..3
    const int ln    = threadIdx.x & 63;          // 0..63
    const int n4    = tile * V4T + ln;
    const bool valid = (n4 < NV_);
    const int cbase = chunk * CCHUNK;

    if (threadIdx.x < CCHUNK) {
        s_tw[threadIdx.x] = theta_w[cbase + threadIdx.x];
        s_gw[threadIdx.x] = g_w[cbase + threadIdx.x];
    }
    __syncthreads();

    const float4* x4 = reinterpret_cast<const float4*>(x) + (size_t)b * CL_ * NV_;

    float  t  = 0.0f;
    float4 g4 = make_float4(0.f, 0.f, 0.f, 0.f);

    if (valid) {
        const int cl0 = gr * CSUB;
        const float4* xp = x4 + (size_t)(cbase + cl0) * NV_ + n4;
        #pragma unroll 8
        for (int c = 0; c < CSUB; c++) {
            float4 v  = __ldg(xp + (size_t)c * NV_);
            float  tw = s_tw[cl0 + c];
            float  gw = s_gw[cl0 + c];
            t = fmaf(v.x + v.y + v.z + v.w, tw, t);
            g4.x = fmaf(v.x, gw, g4.x);
            g4.y = fmaf(v.y, gw, g4.y);
            g4.z = fmaf(v.z, gw, g4.z);
            g4.w = fmaf(v.w, gw, g4.w);
        }
    }

    // combine g across the 4 intra-block c-groups
    s_g[threadIdx.x] = g4;
    __syncthreads();
    if (threadIdx.x < V4T && valid) {
        float4 a  = s_g[threadIdx.x];
        float4 bb = s_g[threadIdx.x + 64];
        float4 cc = s_g[threadIdx.x + 128];
        float4 dd = s_g[threadIdx.x + 192];
        float4 o;
        o.x = a.x + bb.x + cc.x + dd.x;
        o.y = a.y + bb.y + cc.y + dd.y;
        o.z = a.z + bb.z + cc.z + dd.z;
        o.w = a.w + bb.w + cc.w + dd.w;
        d_g4p[(chunk * B_ + b) * NV_ + n4] = o;
    }

    // reduce t across the block -> one partial
    #pragma unroll
    for (int off = 16; off > 0; off >>= 1)
        t += __shfl_down_sync(0xFFFFFFFFu, t, off);
    if ((threadIdx.x & 31) == 0) s_warp[threadIdx.x >> 5] = t;
    __syncthreads();
    if (threadIdx.x == 0) {
        float s = 0.0f;
        #pragma unroll
        for (int w = 0; w < 8; w++) s += s_warp[w];
        d_part[b * NPART + chunk * TILES_R + tile] = s;
    }
}

// Fold: collapse 4 per-chunk g partials into d_g4, and finish the t mean.
// grid 49 x 256 (12544 threads = B_*NV_). All traffic L2-resident.
__global__ __launch_bounds__(256) void fold_kernel()
{
    const int i = blockIdx.x * blockDim.x + threadIdx.x;   // 0 .. B_*NV_-1
    const int stride = B_ * NV_;

    float4 p0 = d_g4p[i];
    float4 p1 = d_g4p[i + stride];
    float4 p2 = d_g4p[i + 2 * stride];
    float4 p3 = d_g4p[i + 3 * stride];
    float4 o;
    o.x = (p0.x + p1.x) + (p2.x + p3.x);
    o.y = (p0.y + p1.y) + (p2.y + p3.y);
    o.z = (p0.z + p1.z) + (p2.z + p3.z);
    o.w = (p0.w + p1.w) + (p2.w + p3.w);
    d_g4[i] = o;

    if (blockIdx.x == 0 && threadIdx.x < B_) {
        float s = 0.0f;
        #pragma unroll
        for (int k = 0; k < NPART; k++) s += d_part[threadIdx.x * NPART + k];
        d_mt[threadIdx.x] = s * (1.0f / (float)N_);
    }
}

// Pass 2 (back to the measured-33.2us structure): 2 loads + 1 store per thread.
// Reverse traversal so first reads hit the L2-resident tail of x from pass 1.
__global__ __launch_bounds__(256) void out_kernel(
    const float* __restrict__ x,
    const float* __restrict__ h_w,
    const float* __restrict__ h_b,
    float* __restrict__ out)
{
    const int total = B_ * CL_ * NV_;                      // 6,422,528 vec4
    const int v = total - 1 - (blockIdx.x * blockDim.x + threadIdx.x);

    const int n4  = v % NV_;
    const int row = v / NV_;          // row = b*CL + c
    const int c   = row % CL_;
    const int b   = row / CL_;

    const float mt  = __ldg(&d_mt[b]);      // uniform per block -> L1 hit
    const float hwc = h_w[c] * mt;
    const float hbc = h_b[c];

    const float4 g4 = d_g4[b * NV_ + n4];
    const float4 x4 = __ldcs(reinterpret_cast<const float4*>(x) + v);   // last use of x

    float4 o;
    o.x = fmaf(g4.x, hwc, x4.x) + hbc;
    o.y = fmaf(g4.y, hwc, x4.y) + hbc;
    o.z = fmaf(g4.z, hwc, x4.z) + hbc;
    o.w = fmaf(g4.w, hwc, x4.w) + hbc;

    __stcs(reinterpret_cast<float4*>(out) + v, o);          // streaming store
}

extern "C" void kernel_launch(void* const* d_in, const int* in_sizes, int n_in,
                              void* d_out, int out_size)
{
    const float* x       = (const float*)d_in[0];
    const float* theta_w = (const float*)d_in[1];
    const float* g_w     = (const float*)d_in[2];
    const float* h_w     = (const float*)d_in[3];
    const float* h_b     = (const float*)d_in[4];
    float*       out     = (float*)d_out;

    dim3 grid1(TILES_R, B_, NCHUNK);       // 13 x 16 x 4 = 832 blocks
    reduce_kernel<<<grid1, 256>>>(x, theta_w, g_w);

    fold_kernel<<<(B_ * NV_) / 256, 256>>>();   // 49 blocks

    const int total_vec4 = B_ * CL_ * NV_; // 6,422,528
    out_kernel<<<total_vec4 / 256, 256>>>(x, h_w, h_b, out);
}